// round 1
// baseline (speedup 1.0000x reference)
#include <cuda_runtime.h>

// TransOp_expm: out[b] = expm(sum_m c[b,m] * psi[m]) @ x[b]
// B ~ 2M, N=3, M=6. Scaling-and-squaring with reduced (but accuracy-preserving)
// parameters: SQUARINGS=5, ORDER=8 (truncation error ~1e-8 rel, threshold 1e-3).

#define NSQ 5
#define NORD 8

__global__ __launch_bounds__(256) void expm_kernel(
    const float* __restrict__ x,
    const float* __restrict__ c,
    const float* __restrict__ psi,
    float* __restrict__ out,
    int B)
{
    __shared__ float s_psi[54];
    if (threadIdx.x < 54) s_psi[threadIdx.x] = psi[threadIdx.x];
    __syncthreads();

    int b = blockIdx.x * blockDim.x + threadIdx.x;
    if (b >= B) return;

    // ---- T = sum_m c[b,m] * psi[m]  (3x3, row-major) ----
    float T[9];
    #pragma unroll
    for (int j = 0; j < 9; j++) T[j] = 0.0f;
    const float* cb = c + b * 6;
    #pragma unroll
    for (int m = 0; m < 6; m++) {
        float cm = __ldg(&cb[m]);
        #pragma unroll
        for (int j = 0; j < 9; j++)
            T[j] = fmaf(cm, s_psi[m * 9 + j], T[j]);
    }

    // ---- scale: A = T / 2^NSQ ----
    const float sc = 1.0f / (float)(1 << NSQ);
    float A[9];
    #pragma unroll
    for (int j = 0; j < 9; j++) A[j] = T[j] * sc;

    // ---- Horner Taylor: E = I + A/NORD; for k = NORD-1..1: E = I + (A/k) @ E ----
    float E[9];
    {
        const float inv0 = 1.0f / (float)NORD;
        #pragma unroll
        for (int j = 0; j < 9; j++) E[j] = A[j] * inv0;
        E[0] += 1.0f; E[4] += 1.0f; E[8] += 1.0f;
    }

    #pragma unroll
    for (int k = NORD - 1; k >= 1; k--) {
        const float invk = 1.0f / (float)k;
        float Ak[9];
        #pragma unroll
        for (int j = 0; j < 9; j++) Ak[j] = A[j] * invk;
        float Mm[9];
        #pragma unroll
        for (int i = 0; i < 3; i++) {
            #pragma unroll
            for (int jj = 0; jj < 3; jj++) {
                float s = (i == jj) ? 1.0f : 0.0f;   // I + ...
                s = fmaf(Ak[i * 3 + 0], E[0 * 3 + jj], s);
                s = fmaf(Ak[i * 3 + 1], E[1 * 3 + jj], s);
                s = fmaf(Ak[i * 3 + 2], E[2 * 3 + jj], s);
                Mm[i * 3 + jj] = s;
            }
        }
        #pragma unroll
        for (int j = 0; j < 9; j++) E[j] = Mm[j];
    }

    // ---- repeated squaring: E = E @ E, NSQ times ----
    #pragma unroll
    for (int sq = 0; sq < NSQ; sq++) {
        float Mm[9];
        #pragma unroll
        for (int i = 0; i < 3; i++) {
            #pragma unroll
            for (int jj = 0; jj < 3; jj++) {
                float t = E[i * 3 + 0] * E[0 * 3 + jj];
                t = fmaf(E[i * 3 + 1], E[1 * 3 + jj], t);
                t = fmaf(E[i * 3 + 2], E[2 * 3 + jj], t);
                Mm[i * 3 + jj] = t;
            }
        }
        #pragma unroll
        for (int j = 0; j < 9; j++) E[j] = Mm[j];
    }

    // ---- y = E @ x ----
    const float* xb = x + b * 3;
    float x0 = __ldg(&xb[0]);
    float x1 = __ldg(&xb[1]);
    float x2 = __ldg(&xb[2]);
    float* ob = out + b * 3;
    ob[0] = fmaf(E[0], x0, fmaf(E[1], x1, E[2] * x2));
    ob[1] = fmaf(E[3], x0, fmaf(E[4], x1, E[5] * x2));
    ob[2] = fmaf(E[6], x0, fmaf(E[7], x1, E[8] * x2));
}

extern "C" void kernel_launch(void* const* d_in, const int* in_sizes, int n_in,
                              void* d_out, int out_size) {
    const float* x   = (const float*)d_in[0];  // [B,3,1]
    const float* c   = (const float*)d_in[1];  // [B,6]
    const float* psi = (const float*)d_in[2];  // [6,3,3]
    float* out = (float*)d_out;                // [B,3]

    int B = in_sizes[0] / 3;
    int threads = 256;
    int blocks = (B + threads - 1) / threads;
    expm_kernel<<<blocks, threads>>>(x, c, psi, out, B);
}

// round 2
// speedup vs baseline: 1.1978x; 1.1978x over previous
#include <cuda_runtime.h>

// TransOp_expm: out[b] = expm(sum_m c[b,m] * psi[m]) @ x[b]
// B ~ 2M, N=3, M=6. f32x2-packed (2 batches/thread) scaling-and-squaring.
// NSQ=4, ORDER=7: worst-tail truncation ~8e-5 rel, threshold 1e-3.

#define NSQ 4
#define NORD 7

typedef unsigned long long ull;

__device__ __forceinline__ ull pk(float lo, float hi) {
    ull r; asm("mov.b64 %0, {%1, %2};" : "=l"(r) : "f"(lo), "f"(hi)); return r;
}
__device__ __forceinline__ void upk(ull v, float& lo, float& hi) {
    asm("mov.b64 {%0, %1}, %2;" : "=f"(lo), "=f"(hi) : "l"(v));
}
__device__ __forceinline__ ull fma2(ull a, ull b, ull c) {
    ull d; asm("fma.rn.f32x2 %0, %1, %2, %3;" : "=l"(d) : "l"(a), "l"(b), "l"(c)); return d;
}
__device__ __forceinline__ ull mul2(ull a, ull b) {
    ull d; asm("mul.rn.f32x2 %0, %1, %2;" : "=l"(d) : "l"(a), "l"(b)); return d;
}

__global__ __launch_bounds__(256) void expm2_kernel(
    const float* __restrict__ x,
    const float* __restrict__ c,
    const float* __restrict__ psi,
    float* __restrict__ out,
    int B)
{
    // psi pre-scaled by 1/2^NSQ, stored as broadcast f32x2 pairs
    __shared__ ull s_psi2[54];
    if (threadIdx.x < 54) {
        float v = psi[threadIdx.x] * (1.0f / (float)(1 << NSQ));
        s_psi2[threadIdx.x] = pk(v, v);
    }
    __syncthreads();

    int t  = blockIdx.x * blockDim.x + threadIdx.x;
    int b0 = 2 * t;
    if (b0 >= B) return;
    bool full = (b0 + 1 < B);

    // ---- load c for the two batches: 12 contiguous floats = 3 x float4 ----
    ull cm[6];
    if (full) {
        const float4* cq = (const float4*)(c + b0 * 6);
        float4 q0 = __ldg(&cq[0]);
        float4 q1 = __ldg(&cq[1]);
        float4 q2 = __ldg(&cq[2]);
        // layout: [c0..c5 of b0, c0..c5 of b1]
        cm[0] = pk(q0.x, q1.z);
        cm[1] = pk(q0.y, q1.w);
        cm[2] = pk(q0.z, q2.x);
        cm[3] = pk(q0.w, q2.y);
        cm[4] = pk(q1.x, q2.z);
        cm[5] = pk(q1.y, q2.w);
    } else {
        const float* cb = c + b0 * 6;
        #pragma unroll
        for (int m = 0; m < 6; m++) { float v = __ldg(&cb[m]); cm[m] = pk(v, v); }
    }

    // ---- A = sum_m cm * (psi_scaled[m])  (both lanes) ----
    ull A[9];
    #pragma unroll
    for (int j = 0; j < 9; j++) A[j] = 0ULL;
    #pragma unroll
    for (int m = 0; m < 6; m++) {
        #pragma unroll
        for (int j = 0; j < 9; j++)
            A[j] = fma2(cm[m], s_psi2[m * 9 + j], A[j]);
    }

    // ---- Horner with factorial coefficients: E = (1/N!)I; E <- (1/k!)I + A@E ----
    const float fact[8] = {1.f, 1.f, 2.f, 6.f, 24.f, 120.f, 720.f, 5040.f};
    ull E[9];
    {
        float cN = 1.0f / fact[NORD];
        ull cNp = pk(cN, cN);
        #pragma unroll
        for (int j = 0; j < 9; j++) E[j] = 0ULL;
        E[0] = cNp; E[4] = cNp; E[8] = cNp;
    }
    #pragma unroll
    for (int k = NORD - 1; k >= 0; k--) {
        float ck = 1.0f / fact[k];
        ull ckp = pk(ck, ck);
        ull Mm[9];
        #pragma unroll
        for (int i = 0; i < 3; i++) {
            #pragma unroll
            for (int jj = 0; jj < 3; jj++) {
                ull s = (i == jj) ? ckp : 0ULL;
                s = fma2(A[i * 3 + 2], E[2 * 3 + jj], s);
                s = fma2(A[i * 3 + 1], E[1 * 3 + jj], s);
                s = fma2(A[i * 3 + 0], E[0 * 3 + jj], s);
                Mm[i * 3 + jj] = s;
            }
        }
        #pragma unroll
        for (int j = 0; j < 9; j++) E[j] = Mm[j];
    }

    // ---- NSQ squarings: E = E @ E ----
    #pragma unroll
    for (int sq = 0; sq < NSQ; sq++) {
        ull Mm[9];
        #pragma unroll
        for (int i = 0; i < 3; i++) {
            #pragma unroll
            for (int jj = 0; jj < 3; jj++) {
                ull s = mul2(E[i * 3 + 0], E[0 * 3 + jj]);
                s = fma2(E[i * 3 + 1], E[1 * 3 + jj], s);
                s = fma2(E[i * 3 + 2], E[2 * 3 + jj], s);
                Mm[i * 3 + jj] = s;
            }
        }
        #pragma unroll
        for (int j = 0; j < 9; j++) E[j] = Mm[j];
    }

    // ---- y = E @ x ----
    if (full) {
        const float2* xq = (const float2*)(x + b0 * 3);
        float2 f0 = __ldg(&xq[0]);   // x0_b0, x1_b0
        float2 f1 = __ldg(&xq[1]);   // x2_b0, x0_b1
        float2 f2 = __ldg(&xq[2]);   // x1_b1, x2_b1
        ull x0p = pk(f0.x, f1.y);
        ull x1p = pk(f0.y, f2.x);
        ull x2p = pk(f1.x, f2.y);

        ull y0 = fma2(E[0], x0p, fma2(E[1], x1p, mul2(E[2], x2p)));
        ull y1 = fma2(E[3], x0p, fma2(E[4], x1p, mul2(E[5], x2p)));
        ull y2 = fma2(E[6], x0p, fma2(E[7], x1p, mul2(E[8], x2p)));

        float y0a, y0b, y1a, y1b, y2a, y2b;
        upk(y0, y0a, y0b); upk(y1, y1a, y1b); upk(y2, y2a, y2b);

        float2* oq = (float2*)(out + b0 * 3);
        oq[0] = make_float2(y0a, y1a);
        oq[1] = make_float2(y2a, y0b);
        oq[2] = make_float2(y1b, y2b);
    } else {
        const float* xb = x + b0 * 3;
        float x0 = __ldg(&xb[0]), x1 = __ldg(&xb[1]), x2 = __ldg(&xb[2]);
        ull x0p = pk(x0, x0), x1p = pk(x1, x1), x2p = pk(x2, x2);
        ull y0 = fma2(E[0], x0p, fma2(E[1], x1p, mul2(E[2], x2p)));
        ull y1 = fma2(E[3], x0p, fma2(E[4], x1p, mul2(E[5], x2p)));
        ull y2 = fma2(E[6], x0p, fma2(E[7], x1p, mul2(E[8], x2p)));
        float ya, yb;
        float* ob = out + b0 * 3;
        upk(y0, ya, yb); ob[0] = ya;
        upk(y1, ya, yb); ob[1] = ya;
        upk(y2, ya, yb); ob[2] = ya;
    }
}

extern "C" void kernel_launch(void* const* d_in, const int* in_sizes, int n_in,
                              void* d_out, int out_size) {
    const float* x   = (const float*)d_in[0];  // [B,3,1]
    const float* c   = (const float*)d_in[1];  // [B,6]
    const float* psi = (const float*)d_in[2];  // [6,3,3]
    float* out = (float*)d_out;                // [B,3]

    int B = in_sizes[0] / 3;
    int pairs = (B + 1) / 2;
    int threads = 256;
    int blocks = (pairs + threads - 1) / threads;
    expm2_kernel<<<blocks, threads>>>(x, c, psi, out, B);
}

// round 3
// speedup vs baseline: 1.6069x; 1.3415x over previous
#include <cuda_runtime.h>

// TransOp_expm via Cayley-Hamilton scalarization.
// out[b] = expm(T_b) @ x_b,  T_b = sum_m c[b,m] psi[m],  3x3, B ~ 2M.
// A = T/2^NSQ. exp(A) ~ a*I + b*A + c*A^2 with (a,b,c) from a scalar Taylor
// recurrence (A^k = x I + y A + z A^2 via char poly), squarings done in
// (a,b,c) space. Two batches per thread, packed f32x2.

#define NSQ 4
#define NORD 8

typedef unsigned long long ull;

__device__ __forceinline__ ull pk(float lo, float hi) {
    ull r; asm("mov.b64 %0, {%1, %2};" : "=l"(r) : "f"(lo), "f"(hi)); return r;
}
__device__ __forceinline__ void upk(ull v, float& lo, float& hi) {
    asm("mov.b64 {%0, %1}, %2;" : "=f"(lo), "=f"(hi) : "l"(v));
}
__device__ __forceinline__ ull fma2(ull a, ull b, ull c) {
    ull d; asm("fma.rn.f32x2 %0, %1, %2, %3;" : "=l"(d) : "l"(a), "l"(b), "l"(c)); return d;
}
__device__ __forceinline__ ull mul2(ull a, ull b) {
    ull d; asm("mul.rn.f32x2 %0, %1, %2;" : "=l"(d) : "l"(a), "l"(b)); return d;
}
__device__ __forceinline__ ull add2(ull a, ull b) {
    ull d; asm("add.rn.f32x2 %0, %1, %2;" : "=l"(d) : "l"(a), "l"(b)); return d;
}

__global__ __launch_bounds__(256) void expmch_kernel(
    const float* __restrict__ x,
    const float* __restrict__ c,
    const float* __restrict__ psi,
    float* __restrict__ out,
    int B)
{
    // psi pre-scaled by 1/2^NSQ, broadcast f32x2
    __shared__ ull s_psi2[54];
    if (threadIdx.x < 54) {
        float v = psi[threadIdx.x] * (1.0f / (float)(1 << NSQ));
        s_psi2[threadIdx.x] = pk(v, v);
    }
    __syncthreads();

    int t  = blockIdx.x * blockDim.x + threadIdx.x;
    int b0 = 2 * t;
    if (b0 >= B) return;
    bool full = (b0 + 1 < B);

    const ull NEG1 = pk(-1.0f, -1.0f);
    const ull HALF = pk(0.5f, 0.5f);
    const ull ONE  = pk(1.0f, 1.0f);

    // ---- load c (two batches, 12 contiguous floats) ----
    ull cm[6];
    if (full) {
        const float4* cq = (const float4*)(c + b0 * 6);
        float4 q0 = __ldg(&cq[0]);
        float4 q1 = __ldg(&cq[1]);
        float4 q2 = __ldg(&cq[2]);
        cm[0] = pk(q0.x, q1.z);
        cm[1] = pk(q0.y, q1.w);
        cm[2] = pk(q0.z, q2.x);
        cm[3] = pk(q0.w, q2.y);
        cm[4] = pk(q1.x, q2.z);
        cm[5] = pk(q1.y, q2.w);
    } else {
        const float* cb = c + b0 * 6;
        #pragma unroll
        for (int m = 0; m < 6; m++) { float v = __ldg(&cb[m]); cm[m] = pk(v, v); }
    }

    // ---- A = sum_m cm * psi_scaled[m] ----
    ull A[9];
    #pragma unroll
    for (int j = 0; j < 9; j++) A[j] = 0ULL;
    #pragma unroll
    for (int m = 0; m < 6; m++) {
        #pragma unroll
        for (int j = 0; j < 9; j++)
            A[j] = fma2(cm[m], s_psi2[m * 9 + j], A[j]);
    }

    // ---- invariants: c1 = tr A, c2 = (c1^2 - tr A^2)/2, c3 = det A ----
    ull c1 = add2(add2(A[0], A[4]), A[8]);
    // diag of A^2
    ull d0 = fma2(A[0], A[0], fma2(A[1], A[3], mul2(A[2], A[6])));
    ull d1 = fma2(A[3], A[1], fma2(A[4], A[4], mul2(A[5], A[7])));
    ull d2 = fma2(A[6], A[2], fma2(A[7], A[5], mul2(A[8], A[8])));
    ull trA2 = add2(add2(d0, d1), d2);
    ull c1sq = mul2(c1, c1);
    // nc2 = -c2 = (trA2 - c1^2)/2 ; c2 = (c1^2 - trA2)/2
    ull nc2 = mul2(fma2(c1sq, NEG1, trA2), HALF);
    // det via minors (m1n is the negated (0,1) minor so all terms add)
    ull m0  = fma2(mul2(A[5], A[7]), NEG1, mul2(A[4], A[8]));   // A4*A8 - A5*A7
    ull m1n = fma2(mul2(A[3], A[8]), NEG1, mul2(A[5], A[6]));   // A5*A6 - A3*A8
    ull m2  = fma2(mul2(A[4], A[6]), NEG1, mul2(A[3], A[7]));   // A3*A7 - A4*A6
    ull c3  = fma2(A[0], m0, fma2(A[1], m1n, mul2(A[2], m2)));
    // squaring-reduction constants: A^4 = k_c A^2 + k_b A + k_a I
    ull k_a = mul2(c1, c3);
    ull k_b = fma2(c1, nc2, c3);        // c3 - c1*c2
    ull k_c = add2(c1sq, nc2);          // c1^2 - c2

    // ---- scalar Taylor: sum_{k=0}^{NORD} A^k/k! = sa*I + sb*A + sc*A^2 ----
    // state (xk,yk,zk) holds A^k; recurrence A^{k+1}: x'=c3 z, y'=x - c2 z, z'=y + c1 z
    ull sa = ONE, sb = ONE, sc = HALF;
    ull xk = 0ULL, yk = 0ULL, zk = ONE;   // A^2
    const float invfact[NORD + 1] = {
        1.f, 1.f, 0.5f,
        1.f/6.f, 1.f/24.f, 1.f/120.f, 1.f/720.f, 1.f/5040.f, 1.f/40320.f
    };
    #pragma unroll
    for (int k = 3; k <= NORD; k++) {
        ull xn = mul2(c3, zk);
        ull yn = fma2(nc2, zk, xk);
        ull zn = fma2(c1, zk, yk);
        ull cf = pk(invfact[k], invfact[k]);
        sa = fma2(xn, cf, sa);
        sb = fma2(yn, cf, sb);
        sc = fma2(zn, cf, sc);
        xk = xn; yk = yn; zk = zn;
    }

    // ---- NSQ squarings in coefficient space ----
    #pragma unroll
    for (int sq = 0; sq < NSQ; sq++) {
        ull t_aa = mul2(sa, sa);
        ull t_bb = mul2(sb, sb);
        ull t_cc = mul2(sc, sc);
        ull t_ab = mul2(sa, sb);
        ull t_ac = mul2(sa, sc);
        ull t_bc = mul2(sb, sc);
        ull t2ab = add2(t_ab, t_ab);
        ull t2ac = add2(t_ac, t_ac);
        ull t2bc = add2(t_bc, t_bc);
        ull na = fma2(t_cc, k_a, fma2(t2bc, c3,  t_aa));
        ull nb = fma2(t_cc, k_b, fma2(t2bc, nc2, t2ab));
        ull nc = fma2(t_cc, k_c, fma2(t2bc, c1,  add2(t_bb, t2ac)));
        sa = na; sb = nb; sc = nc;
    }

    // ---- y = sa*x + sb*(A x) + sc*(A (A x)) ----
    ull v0, v1, v2;
    if (full) {
        const float2* xq = (const float2*)(x + b0 * 3);
        float2 f0 = __ldg(&xq[0]);
        float2 f1 = __ldg(&xq[1]);
        float2 f2 = __ldg(&xq[2]);
        v0 = pk(f0.x, f1.y);
        v1 = pk(f0.y, f2.x);
        v2 = pk(f1.x, f2.y);
    } else {
        const float* xb = x + b0 * 3;
        float x0 = __ldg(&xb[0]), x1 = __ldg(&xb[1]), x2 = __ldg(&xb[2]);
        v0 = pk(x0, x0); v1 = pk(x1, x1); v2 = pk(x2, x2);
    }

    ull w0 = fma2(A[0], v0, fma2(A[1], v1, mul2(A[2], v2)));
    ull w1 = fma2(A[3], v0, fma2(A[4], v1, mul2(A[5], v2)));
    ull w2 = fma2(A[6], v0, fma2(A[7], v1, mul2(A[8], v2)));

    ull u0 = fma2(A[0], w0, fma2(A[1], w1, mul2(A[2], w2)));
    ull u1 = fma2(A[3], w0, fma2(A[4], w1, mul2(A[5], w2)));
    ull u2 = fma2(A[6], w0, fma2(A[7], w1, mul2(A[8], w2)));

    ull y0 = fma2(sa, v0, fma2(sb, w0, mul2(sc, u0)));
    ull y1 = fma2(sa, v1, fma2(sb, w1, mul2(sc, u1)));
    ull y2 = fma2(sa, v2, fma2(sb, w2, mul2(sc, u2)));

    if (full) {
        float y0a, y0b, y1a, y1b, y2a, y2b;
        upk(y0, y0a, y0b); upk(y1, y1a, y1b); upk(y2, y2a, y2b);
        float2* oq = (float2*)(out + b0 * 3);
        oq[0] = make_float2(y0a, y1a);
        oq[1] = make_float2(y2a, y0b);
        oq[2] = make_float2(y1b, y2b);
    } else {
        float ya, yb;
        float* ob = out + b0 * 3;
        upk(y0, ya, yb); ob[0] = ya;
        upk(y1, ya, yb); ob[1] = ya;
        upk(y2, ya, yb); ob[2] = ya;
    }
}

extern "C" void kernel_launch(void* const* d_in, const int* in_sizes, int n_in,
                              void* d_out, int out_size) {
    const float* x   = (const float*)d_in[0];  // [B,3,1]
    const float* c   = (const float*)d_in[1];  // [B,6]
    const float* psi = (const float*)d_in[2];  // [6,3,3]
    float* out = (float*)d_out;                // [B,3]

    int B = in_sizes[0] / 3;
    int pairs = (B + 1) / 2;
    int threads = 256;
    int blocks = (pairs + threads - 1) / threads;
    expmch_kernel<<<blocks, threads>>>(x, c, psi, out, B);
}